// round 16
// baseline (speedup 1.0000x reference)
#include <cuda_runtime.h>
#include <cuda_fp16.h>
#include <math.h>
#include <stdint.h>

// ---------------- problem constants ----------------
#define S     4096
#define DM    768
#define FF    3072
#define HNUM  12
#define HD    64
#define WIN   256
#define CCH   16
#define NW    8
#define LNUM  12
#define OUTD  128
#define SCALE 0.125f

// ---------------- scratch ----------------
__device__ float g_h    [S*DM];
__device__ float g_y0   [S*DM];
__device__ __half g_h16   [S*DM];
__device__ __half g_q16   [S*DM];
__device__ __half g_k16   [S*DM];
__device__ __half g_v16   [S*DM];
__device__ __half g_kg16  [S*DM];
__device__ __half g_vg16  [S*DM];
__device__ __half g_attn16[S*DM];
__device__ __half g_ffn16 [S*FF];

// fp16 weight copies
__device__ __half g_hWq [LNUM*DM*DM];
__device__ __half g_hWk [LNUM*DM*DM];
__device__ __half g_hWv [LNUM*DM*DM];
__device__ __half g_hWo [LNUM*DM*DM];
__device__ __half g_hWkg[LNUM*DM*DM];
__device__ __half g_hWvg[LNUM*DM*DM];
__device__ __half g_hW1 [LNUM*DM*FF];
__device__ __half g_hW2 [LNUM*FF*DM];

// ---------------- helpers ----------------
__device__ __forceinline__ float gelu_f(float x) {
    float x3 = x * x * x;
    return 0.5f * x * (1.0f + tanhf(0.7978845608028654f * (x + 0.044715f * x3)));
}

__device__ __forceinline__ unsigned pack_h2(float a, float b) {
    __half2 p = __float22half2_rn(make_float2(a, b));
    return *reinterpret_cast<unsigned*>(&p);
}

__device__ __forceinline__ void cp_async16(void* smem_dst, const void* gmem_src) {
    uint32_t dst = (uint32_t)__cvta_generic_to_shared(smem_dst);
    asm volatile("cp.async.ca.shared.global [%0], [%1], 16;" :: "r"(dst), "l"(gmem_src));
}

__device__ __forceinline__ void cp_async16z(void* smem_dst, const void* gmem_src, int src_sz) {
    uint32_t dst = (uint32_t)__cvta_generic_to_shared(smem_dst);
    asm volatile("cp.async.ca.shared.global [%0], [%1], 16, %2;"
                 :: "r"(dst), "l"(gmem_src), "r"(src_sz));
}

// ---------------- fp32 -> fp16 conversion, batched over z ----------------
__global__ void f2h_kernel6(const float4* in0, const float4* in1, const float4* in2,
                            const float4* in3, const float4* in4, const float4* in5,
                            uint2* out0, uint2* out1, uint2* out2,
                            uint2* out3, uint2* out4, uint2* out5, int n4)
{
    int z = blockIdx.z;
    const float4* in = (z == 0) ? in0 : (z == 1) ? in1 : (z == 2) ? in2 :
                       (z == 3) ? in3 : (z == 4) ? in4 : in5;
    uint2* out = (z == 0) ? out0 : (z == 1) ? out1 : (z == 2) ? out2 :
                 (z == 3) ? out3 : (z == 4) ? out4 : out5;
    for (int i = blockIdx.x * blockDim.x + threadIdx.x; i < n4; i += gridDim.x * blockDim.x) {
        float4 v = in[i];
        uint2 o;
        o.x = pack_h2(v.x, v.y);
        o.y = pack_h2(v.z, v.w);
        out[i] = o;
    }
}

__global__ void f2h_kernel(const float4* __restrict__ in, uint2* __restrict__ out, int n4)
{
    for (int i = blockIdx.x * blockDim.x + threadIdx.x; i < n4; i += gridDim.x * blockDim.x) {
        float4 v = in[i];
        uint2 o;
        o.x = pack_h2(v.x, v.y);
        o.y = pack_h2(v.z, v.w);
        out[i] = o;
    }
}

// ---------------- LN core ----------------
__device__ __forceinline__ void ln_write(float4 v, const float4* __restrict__ ls4,
                                         const float4* __restrict__ lb4,
                                         float4* __restrict__ o, uint2* __restrict__ o16,
                                         size_t idx, int t)
{
    const int warp = t >> 5, lane = t & 31;
    __shared__ float ss[6], ss2[6];
    float sum = v.x + v.y + v.z + v.w;
    float sq  = v.x * v.x + v.y * v.y + v.z * v.z + v.w * v.w;
#pragma unroll
    for (int o_ = 16; o_ > 0; o_ >>= 1) {
        sum += __shfl_xor_sync(0xffffffffu, sum, o_);
        sq  += __shfl_xor_sync(0xffffffffu, sq,  o_);
    }
    if (lane == 0) { ss[warp] = sum; ss2[warp] = sq; }
    __syncthreads();
    float tot  = ss[0] + ss[1] + ss[2] + ss[3] + ss[4] + ss[5];
    float tot2 = ss2[0] + ss2[1] + ss2[2] + ss2[3] + ss2[4] + ss2[5];
    float mean = tot * (1.f / (float)DM);
    float var  = tot2 * (1.f / (float)DM) - mean * mean;
    float rstd = rsqrtf(var + 1e-5f);
    float4 lsv = ls4[t], lbv = lb4[t];
    float4 ov;
    ov.x = (v.x - mean) * rstd * lsv.x + lbv.x;
    ov.y = (v.y - mean) * rstd * lsv.y + lbv.y;
    ov.z = (v.z - mean) * rstd * lsv.z + lbv.z;
    ov.w = (v.w - mean) * rstd * lsv.w + lbv.w;
    o[idx] = ov;
    uint2 pk;
    pk.x = pack_h2(ov.x, ov.y);
    pk.y = pack_h2(ov.z, ov.w);
    o16[idx] = pk;
}

// ---------------- embedding + LN ----------------
__global__ void embed_kernel(const int* __restrict__ x, const float4* __restrict__ we,
                             const float4* __restrict__ pe, const float4* __restrict__ ls,
                             const float4* __restrict__ lb, float4* __restrict__ h,
                             uint2* __restrict__ h16)
{
    int s = blockIdx.x;
    int t = threadIdx.x;
    int r = s & 511, w = s >> 9;
    int id = (r == 0) ? 0 : x[w * 511 + r - 1];
    float4 a = we[(size_t)id * 192 + t];
    float4 b = pe[(size_t)s * 192 + t];
    float4 v = make_float4(a.x + b.x, a.y + b.y, a.z + b.z, a.w + b.w);
    ln_write(v, ls, lb, h, h16, (size_t)s * 192 + t, t);
}

// ---------------- residual add + LN ----------------
__global__ void add_ln_kernel(const float4* __restrict__ x, const float4* __restrict__ y,
                              const float4* __restrict__ ls, const float4* __restrict__ lb,
                              float4* __restrict__ o, uint2* __restrict__ o16)
{
    int s = blockIdx.x;
    int t = threadIdx.x;
    size_t idx = (size_t)s * 192 + t;
    float4 a = x[idx], b = y[idx];
    float4 v = make_float4(a.x + b.x, a.y + b.y, a.z + b.z, a.w + b.w);
    ln_write(v, ls, lb, o, o16, idx, t);
}

// ---------------- fp16 tensor-core GEMM, cp.async 2-stage, batched over z ----------------
#define AS_H    9216
#define STG_H   17920
#define TGEMM_SMEM (2 * STG_H * 2)

__global__ __launch_bounds__(256, 2)
void hgemm_kernel(const __half* __restrict__ A,
                  const __half* B0, const __half* B1, const __half* B2,
                  const __half* B3, const __half* B4,
                  const float* bias0, const float* bias1, const float* bias2,
                  const float* bias3, const float* bias4,
                  void* C0, void* C1, void* C2, void* C3, void* C4,
                  int M, int N, int K, int lda, int aZstride,
                  float al0, int act, int outHalfMask)
{
    extern __shared__ __half sm[];

    const int z = blockIdx.z;
    const __half* B = (z == 0) ? B0 : (z == 1) ? B1 : (z == 2) ? B2 : (z == 3) ? B3 : B4;
    const float* bias = (z == 0) ? bias0 : (z == 1) ? bias1 : (z == 2) ? bias2 : (z == 3) ? bias3 : bias4;
    void* C = (z == 0) ? C0 : (z == 1) ? C1 : (z == 2) ? C2 : (z == 3) ? C3 : C4;
    const float alpha = (z == 0) ? al0 : 1.0f;
    const int outHalf = (outHalfMask >> z) & 1;

    A += (size_t)z * aZstride;

    const int tid  = threadIdx.x;
    const int lane = tid & 31;
    const int warp = tid >> 5;
    const int wm = warp >> 2;
    const int wn = warp & 3;

    const int bRow = blockIdx.y * 128;
    const int bCol = blockIdx.x * 128;

    float acc[4][4][4];
#pragma unroll
    for (int i = 0; i < 4; i++)
#pragma unroll
        for (int j = 0; j < 4; j++)
#pragma unroll
            for (int r = 0; r < 4; r++) acc[i][j][r] = 0.f;

    const int nk = K >> 6;

    {
        __half* as = sm;
        __half* bs = sm + AS_H;
#pragma unroll
        for (int p = 0; p < 4; p++) {
            int id = p * 256 + tid;
            int r = id >> 3, c = (id & 7) * 8;
            cp_async16(as + r * 72 + c, A + (size_t)(bRow + r) * lda + c);
        }
#pragma unroll
        for (int p = 0; p < 4; p++) {
            int id = p * 256 + tid;
            int r = id >> 4, c = (id & 15) * 8;
            cp_async16(bs + r * 136 + c, B + (size_t)r * N + bCol + c);
        }
        asm volatile("cp.async.commit_group;" ::);
    }

    for (int kt = 0; kt < nk; kt++) {
        asm volatile("cp.async.wait_group 0;" ::);
        __syncthreads();

        if (kt + 1 < nk) {
            const int k0 = (kt + 1) << 6;
            __half* as = sm + ((kt + 1) & 1) * STG_H;
            __half* bs = as + AS_H;
#pragma unroll
            for (int p = 0; p < 4; p++) {
                int id = p * 256 + tid;
                int r = id >> 3, c = (id & 7) * 8;
                cp_async16(as + r * 72 + c, A + (size_t)(bRow + r) * lda + k0 + c);
            }
#pragma unroll
            for (int p = 0; p < 4; p++) {
                int id = p * 256 + tid;
                int r = id >> 4, c = (id & 15) * 8;
                cp_async16(bs + r * 136 + c, B + (size_t)(k0 + r) * N + bCol + c);
            }
            asm volatile("cp.async.commit_group;" ::);
        }

        const __half* as = sm + (kt & 1) * STG_H;
        const __half* bs = as + AS_H;
#pragma unroll
        for (int kk = 0; kk < 64; kk += 16) {
            uint32_t af[4][4];
#pragma unroll
            for (int mi = 0; mi < 4; mi++) {
                uint32_t addr = (uint32_t)__cvta_generic_to_shared(
                    as + (wm * 64 + mi * 16 + (lane & 15)) * 72 + kk + (lane >> 4) * 8);
                asm volatile("ldmatrix.sync.aligned.m8n8.x4.shared.b16 {%0,%1,%2,%3}, [%4];"
                             : "=r"(af[mi][0]), "=r"(af[mi][1]), "=r"(af[mi][2]), "=r"(af[mi][3])
                             : "r"(addr));
            }
            uint32_t bfr[4][2];
#pragma unroll
            for (int nb = 0; nb < 2; nb++) {
                uint32_t addr = (uint32_t)__cvta_generic_to_shared(
                    bs + (kk + (lane & 15)) * 136 + wn * 32 + nb * 16 + (lane >> 4) * 8);
                uint32_t r0, r1, r2, r3;
                asm volatile("ldmatrix.sync.aligned.m8n8.x4.trans.shared.b16 {%0,%1,%2,%3}, [%4];"
                             : "=r"(r0), "=r"(r1), "=r"(r2), "=r"(r3)
                             : "r"(addr));
                bfr[nb * 2][0] = r0; bfr[nb * 2][1] = r1;
                bfr[nb * 2 + 1][0] = r2; bfr[nb * 2 + 1][1] = r3;
            }
#pragma unroll
            for (int mi = 0; mi < 4; mi++)
#pragma unroll
                for (int ni = 0; ni < 4; ni++) {
                    asm volatile(
                        "mma.sync.aligned.m16n8k16.row.col.f32.f16.f16.f32 "
                        "{%0,%1,%2,%3}, {%4,%5,%6,%7}, {%8,%9}, {%0,%1,%2,%3};"
                        : "+f"(acc[mi][ni][0]), "+f"(acc[mi][ni][1]),
                          "+f"(acc[mi][ni][2]), "+f"(acc[mi][ni][3])
                        : "r"(af[mi][0]), "r"(af[mi][1]), "r"(af[mi][2]), "r"(af[mi][3]),
                          "r"(bfr[ni][0]), "r"(bfr[ni][1]));
                }
        }
        __syncthreads();
    }

#pragma unroll
    for (int mi = 0; mi < 4; mi++) {
        int row0 = bRow + wm * 64 + mi * 16 + (lane >> 2);
#pragma unroll
        for (int ni = 0; ni < 4; ni++) {
            int col = bCol + wn * 32 + ni * 8 + (lane & 3) * 2;
            float b0 = bias[col], b1 = bias[col + 1];
            float v0 = (acc[mi][ni][0] + b0) * alpha;
            float v1 = (acc[mi][ni][1] + b1) * alpha;
            float v2 = (acc[mi][ni][2] + b0) * alpha;
            float v3 = (acc[mi][ni][3] + b1) * alpha;
            if (act == 1) { v0 = gelu_f(v0); v1 = gelu_f(v1); v2 = gelu_f(v2); v3 = gelu_f(v3); }
            if (outHalf) {
                __half* Ch = (__half*)C;
                *(uint32_t*)&Ch[(size_t)row0 * N + col]       = pack_h2(v0, v1);
                *(uint32_t*)&Ch[(size_t)(row0 + 8) * N + col] = pack_h2(v2, v3);
            } else {
                float* Cf = (float*)C;
                *(float2*)&Cf[(size_t)row0 * N + col]       = make_float2(v0, v1);
                *(float2*)&Cf[(size_t)(row0 + 8) * N + col] = make_float2(v2, v3);
            }
        }
    }
}

// ---------------- merged attention: local (bx<32) + global (bx>=32) ----------------
#define ATTN_SMEM_BYTES 36864

__global__ __launch_bounds__(256)
void attn_kernel(const __half* __restrict__ q, const __half* __restrict__ k,
                 const __half* __restrict__ v,
                 const float* __restrict__ h, const float* __restrict__ Wqg,
                 const float* __restrict__ bqg,
                 const __half* __restrict__ kg, const __half* __restrict__ vg,
                 __half* __restrict__ out)
{
    __shared__ __align__(16) char smraw[ATTN_SMEM_BYTES];
    const int bx = blockIdx.x;
    const int hh = blockIdx.y;
    const int tid = threadIdx.x;
    const int hoff = hh * HD;

    if (bx < 32) {
        typedef __half Row72[72];
        Row72* Qs  = (Row72*)smraw;                 // [128][72]
        Row72* Ks0 = (Row72*)(smraw + 18432);       // [2*32][72]
        Row72* Vs0 = (Row72*)(smraw + 27648);       // [2*32][72]
        const int c = bx >> 1, half = bx & 1;
        const int lane = tid & 31, warp = tid >> 5;
        const int qbase = c * WIN + half * 128;

        const int st_hs = tid >> 7;
        const int st_j  = (tid & 127) >> 3;
        const int st_ch = (tid & 7) * 8;

        for (int i = tid; i < 1024; i += 256) {
            int row = i >> 3, ch = (i & 7) * 8;
            *(uint4*)&Qs[row][ch] = *(const uint4*)&q[(size_t)(qbase + row) * DM + hoff + ch];
        }

        {
            const __half* src = st_hs ? v : k;
#pragma unroll
            for (int rr = 0; rr < 2; rr++) {
                int row = st_j + rr * 16;
                bool valid = (row < 8);
                int kpos = valid ? row * 512 : 0;
                void* dst = st_hs ? (void*)&Vs0[row][st_ch] : (void*)&Ks0[row][st_ch];
                cp_async16z(dst, src + (size_t)kpos * DM + hoff + st_ch, valid ? 16 : 0);
            }
            asm volatile("cp.async.commit_group;" ::);
        }
        __syncthreads();

        uint32_t qf[4][4];
#pragma unroll
        for (int kt = 0; kt < 4; kt++) {
            uint32_t addr = (uint32_t)__cvta_generic_to_shared(
                &Qs[warp * 16 + (lane & 15)][kt * 16 + (lane >> 4) * 8]);
            asm volatile("ldmatrix.sync.aligned.m8n8.x4.shared.b16 {%0,%1,%2,%3}, [%4];"
                         : "=r"(qf[kt][0]), "=r"(qf[kt][1]), "=r"(qf[kt][2]), "=r"(qf[kt][3])
                         : "r"(addr));
        }

        float mrow[2] = { -1e30f, -1e30f }, lrow[2] = { 0.f, 0.f };
        float acc[8][4];
#pragma unroll
        for (int n8 = 0; n8 < 8; n8++)
#pragma unroll
            for (int r = 0; r < 4; r++) acc[n8][r] = 0.f;

        for (int t0 = 0; t0 <= 24; t0++) {
            const int cur = t0 & 1, nxt = cur ^ 1;

            asm volatile("cp.async.wait_group 0;" ::);
            __syncthreads();

            if (t0 < 24) {
                const __half* src = st_hs ? v : k;
#pragma unroll
                for (int rr = 0; rr < 2; rr++) {
                    int row = st_j + rr * 16;
                    int jg = t0 * 32 + row;
                    int kpos = c * WIN + jg - WIN;
                    bool valid = (kpos >= 0 && kpos < S);
                    void* dst = st_hs ? (void*)&Vs0[nxt * 32 + row][st_ch]
                                      : (void*)&Ks0[nxt * 32 + row][st_ch];
                    cp_async16z(dst, src + (size_t)(valid ? kpos : 0) * DM + hoff + st_ch,
                                valid ? 16 : 0);
                }
            }
            asm volatile("cp.async.commit_group;" ::);

            float sc[4][4];
#pragma unroll
            for (int nb = 0; nb < 4; nb++)
#pragma unroll
                for (int r = 0; r < 4; r++) sc[nb][r] = 0.f;
#pragma unroll
            for (int g = 0; g < 2; g++) {
                uint32_t kf[4][4];
#pragma unroll
                for (int kt = 0; kt < 4; kt++) {
                    uint32_t addr = (uint32_t)__cvta_generic_to_shared(
                        &Ks0[cur * 32 + g * 16 + (lane & 15)][kt * 16 + (lane >> 4) * 8]);
                    asm volatile("ldmatrix.sync.aligned.m8n8.x4.shared.b16 {%0,%1,%2,%3}, [%4];"
                                 : "=r"(kf[kt][0]), "=r"(kf[kt][1]), "=r"(kf[kt][2]), "=r"(kf[kt][3])
                                 : "r"(addr));
                }
#pragma unroll
                for (int kt = 0; kt < 4; kt++) {
                    asm volatile(
                        "mma.sync.aligned.m16n8k16.row.col.f32.f16.f16.f32 "
                        "{%0,%1,%2,%3}, {%4,%5,%6,%7}, {%8,%9}, {%0,%1,%2,%3};"
                        : "+f"(sc[g*2][0]), "+f"(sc[g*2][1]), "+f"(sc[g*2][2]), "+f"(sc[g*2][3])
                        : "r"(qf[kt][0]), "r"(qf[kt][1]), "r"(qf[kt][2]), "r"(qf[kt][3]),
                          "r"(kf[kt][0]), "r"(kf[kt][2]));
                    asm volatile(
                        "mma.sync.aligned.m16n8k16.row.col.f32.f16.f16.f32 "
                        "{%0,%1,%2,%3}, {%4,%5,%6,%7}, {%8,%9}, {%0,%1,%2,%3};"
                        : "+f"(sc[g*2+1][0]), "+f"(sc[g*2+1][1]), "+f"(sc[g*2+1][2]), "+f"(sc[g*2+1][3])
                        : "r"(qf[kt][0]), "r"(qf[kt][1]), "r"(qf[kt][2]), "r"(qf[kt][3]),
                          "r"(kf[kt][1]), "r"(kf[kt][3]));
                }
            }

            uint32_t pa[2][4];
#pragma unroll
            for (int hq = 0; hq < 2; hq++) {
                int qi = half * 128 + warp * 16 + (lane >> 2) + hq * 8;
                int j0 = (lane & 3) * 2;
                float sv[8];
#pragma unroll
                for (int nb = 0; nb < 4; nb++) {
                    sv[nb * 2]     = sc[nb][2 * hq];
                    sv[nb * 2 + 1] = sc[nb][2 * hq + 1];
                }
#pragma unroll
                for (int e = 0; e < 8; e++) {
                    int jj = (e >> 1) * 8 + j0 + (e & 1);
                    bool valid;
                    if (t0 == 0) valid = (jj < 8);
                    else {
                        int jg = (t0 - 1) * 32 + jj;
                        int kp = c * WIN + jg - WIN;
                        valid = (jg >= qi) && (jg <= qi + 2 * WIN) && (kp >= 0) && (kp < S);
                    }
                    if (!valid) sv[e] = -1e30f;
                }
                float rmax = sv[0];
#pragma unroll
                for (int e = 1; e < 8; e++) rmax = fmaxf(rmax, sv[e]);
                rmax = fmaxf(rmax, __shfl_xor_sync(0xffffffffu, rmax, 1));
                rmax = fmaxf(rmax, __shfl_xor_sync(0xffffffffu, rmax, 2));
                float mnew = fmaxf(mrow[hq], rmax);
                float scale = __expf(mrow[hq] - mnew);
                float p[8], ls = 0.f;
#pragma unroll
                for (int e = 0; e < 8; e++) { p[e] = __expf(sv[e] - mnew); ls += p[e]; }
                ls += __shfl_xor_sync(0xffffffffu, ls, 1);
                ls += __shfl_xor_sync(0xffffffffu, ls, 2);
                lrow[hq] = lrow[hq] * scale + ls;
                mrow[hq] = mnew;
#pragma unroll
                for (int n8 = 0; n8 < 8; n8++) {
                    acc[n8][2 * hq]     *= scale;
                    acc[n8][2 * hq + 1] *= scale;
                }
                pa[0][hq]     = pack_h2(p[0], p[1]);
                pa[0][hq + 2] = pack_h2(p[2], p[3]);
                pa[1][hq]     = pack_h2(p[4], p[5]);
                pa[1][hq + 2] = pack_h2(p[6], p[7]);
            }

#pragma unroll
            for (int ks = 0; ks < 2; ks++) {
#pragma unroll
                for (int nb = 0; nb < 4; nb++) {
                    uint32_t addr = (uint32_t)__cvta_generic_to_shared(
                        &Vs0[cur * 32 + ks * 16 + (lane & 15)][nb * 16 + (lane >> 4) * 8]);
                    uint32_t r0, r1, r2, r3;
                    asm volatile("ldmatrix.sync.aligned.m8n8.x4.trans.shared.b16 {%0,%1,%2,%3}, [%4];"
                                 : "=r"(r0), "=r"(r1), "=r"(r2), "=r"(r3)
                                 : "r"(addr));
                    asm volatile(
                        "mma.sync.aligned.m16n8k16.row.col.f32.f16.f16.f32 "
                        "{%0,%1,%2,%3}, {%4,%5,%6,%7}, {%8,%9}, {%0,%1,%2,%3};"
                        : "+f"(acc[nb*2][0]), "+f"(acc[nb*2][1]), "+f"(acc[nb*2][2]), "+f"(acc[nb*2][3])
                        : "r"(pa[ks][0]), "r"(pa[ks][1]), "r"(pa[ks][2]), "r"(pa[ks][3]),
                          "r"(r0), "r"(r1));
                    asm volatile(
                        "mma.sync.aligned.m16n8k16.row.col.f32.f16.f16.f32 "
                        "{%0,%1,%2,%3}, {%4,%5,%6,%7}, {%8,%9}, {%0,%1,%2,%3};"
                        : "+f"(acc[nb*2+1][0]), "+f"(acc[nb*2+1][1]), "+f"(acc[nb*2+1][2]), "+f"(acc[nb*2+1][3])
                        : "r"(pa[ks][0]), "r"(pa[ks][1]), "r"(pa[ks][2]), "r"(pa[ks][3]),
                          "r"(r2), "r"(r3));
                }
            }
        }

#pragma unroll
        for (int hq = 0; hq < 2; hq++) {
            float inv = 1.f / lrow[hq];
            int row = warp * 16 + (lane >> 2) + hq * 8;
            size_t base = (size_t)(qbase + row) * DM + hoff;
#pragma unroll
            for (int n8 = 0; n8 < 8; n8++) {
                int dim = n8 * 8 + (lane & 3) * 2;
                *(uint32_t*)&out[base + dim] =
                    pack_h2(acc[n8][2 * hq] * inv, acc[n8][2 * hq + 1] * inv);
            }
        }
    } else {
        // global-token attention for g = bx - 32
        float* qs  = (float*)smraw;
        float* sc  = qs + 64;
        float* red = sc + S;
        const int g = bx - 32;

        {
            int d = tid & 63, part = tid >> 6;
            const float* hr = h + (size_t)(g * 512) * DM;
            float a = 0.f;
            for (int kk = part * 192; kk < (part + 1) * 192; kk++)
                a += hr[kk] * Wqg[(size_t)kk * DM + hoff + d];
            red[tid] = a; __syncthreads();
            if (tid < 64)
                qs[tid] = (red[tid] + red[tid + 64] + red[tid + 128] + red[tid + 192]
                           + bqg[hoff + tid]) * SCALE;
            __syncthreads();
        }

        float lmax = -1e30f;
        for (int i = 0; i < 16; i++) {
            int s = i * 256 + tid;
            const __half2* kr = (const __half2*)(kg + (size_t)s * DM + hoff);
            float a = 0.f;
#pragma unroll
            for (int d2 = 0; d2 < 32; d2++) {
                float2 f = __half22float2(kr[d2]);
                a += qs[d2 * 2] * f.x + qs[d2 * 2 + 1] * f.y;
            }
            sc[s] = a;
            lmax = fmaxf(lmax, a);
        }
        red[tid] = lmax; __syncthreads();
        for (int o = 128; o > 0; o >>= 1) { if (tid < o) red[tid] = fmaxf(red[tid], red[tid + o]); __syncthreads(); }
        float mx = red[0]; __syncthreads();

        float lsum = 0.f;
        for (int i = 0; i < 16; i++) {
            int s = i * 256 + tid;
            float p = __expf(sc[s] - mx);
            sc[s] = p;
            lsum += p;
        }
        red[tid] = lsum; __syncthreads();
        for (int o = 128; o > 0; o >>= 1) { if (tid < o) red[tid] += red[tid + o]; __syncthreads(); }
        float inv = 1.f / red[0]; __syncthreads();

        int d = tid & 63;
        int part = tid >> 6;
        float a = 0.f;
        for (int s = part * 1024; s < (part + 1) * 1024; s++)
            a += sc[s] * __half2float(vg[(size_t)s * DM + hoff + d]);
        red[tid] = a; __syncthreads();
        if (tid < 64) {
            float r = red[tid] + red[tid + 64] + red[tid + 128] + red[tid + 192];
            out[(size_t)(g * 512) * DM + hoff + d] = __float2half(r * inv);
        }
    }
}

// ---------------- output head ----------------
__global__ void head_kernel(const float* __restrict__ h, const float* __restrict__ Wout,
                            const float* __restrict__ bout, float* __restrict__ out)
{
    int g = blockIdx.x;
    int o = threadIdx.x;
    const float* hr = h + (size_t)(g * 512) * DM;
    float a = bout[o];
    for (int d = 0; d < DM; d++) a += hr[d] * Wout[(size_t)d * OUTD + o];
    out[g * OUTD + o] = a;
}

// ---------------- driver ----------------
extern "C" void kernel_launch(void* const* d_in, const int* in_sizes, int n_in,
                              void* d_out, int out_size)
{
    (void)in_sizes; (void)n_in; (void)out_size;
    const int*   x        = (const int*)  d_in[0];
    const float* word_emb = (const float*)d_in[1];
    const float* pos_emb  = (const float*)d_in[2];
    const float* emb_ln_s = (const float*)d_in[3];
    const float* emb_ln_b = (const float*)d_in[4];
    const float* Wq  = (const float*)d_in[5];   const float* bq  = (const float*)d_in[6];
    const float* Wk  = (const float*)d_in[7];   const float* bk  = (const float*)d_in[8];
    const float* Wv  = (const float*)d_in[9];   const float* bv  = (const float*)d_in[10];
    const float* Wo  = (const float*)d_in[11];  const float* bo  = (const float*)d_in[12];
    const float* Wqg = (const float*)d_in[13];  const float* bqg = (const float*)d_in[14];
    const float* Wkg = (const float*)d_in[15];  const float* bkg = (const float*)d_in[16];
    const float* Wvg = (const float*)d_in[17];  const float* bvg = (const float*)d_in[18];
    const float* ln1s= (const float*)d_in[19];  const float* ln1b= (const float*)d_in[20];
    const float* W1  = (const float*)d_in[21];  const float* b1  = (const float*)d_in[22];
    const float* W2  = (const float*)d_in[23];  const float* b2  = (const float*)d_in[24];
    const float* ln2s= (const float*)d_in[25];  const float* ln2b= (const float*)d_in[26];
    const float* Wout= (const float*)d_in[27];  const float* bout= (const float*)d_in[28];
    float* out = (float*)d_out;

    float *h, *y0;
    __half *h16, *q16, *k16, *v16, *kg16, *vg16, *attn16, *ffn16;
    cudaGetSymbolAddress((void**)&h,    g_h);
    cudaGetSymbolAddress((void**)&y0,   g_y0);
    cudaGetSymbolAddress((void**)&h16,    g_h16);
    cudaGetSymbolAddress((void**)&q16,    g_q16);
    cudaGetSymbolAddress((void**)&k16,    g_k16);
    cudaGetSymbolAddress((void**)&v16,    g_v16);
    cudaGetSymbolAddress((void**)&kg16,   g_kg16);
    cudaGetSymbolAddress((void**)&vg16,   g_vg16);
    cudaGetSymbolAddress((void**)&attn16, g_attn16);
    cudaGetSymbolAddress((void**)&ffn16,  g_ffn16);

    __half *hWq, *hWk, *hWv, *hWo, *hWkg, *hWvg, *hW1, *hW2;
    cudaGetSymbolAddress((void**)&hWq,  g_hWq);
    cudaGetSymbolAddress((void**)&hWk,  g_hWk);
    cudaGetSymbolAddress((void**)&hWv,  g_hWv);
    cudaGetSymbolAddress((void**)&hWo,  g_hWo);
    cudaGetSymbolAddress((void**)&hWkg, g_hWkg);
    cudaGetSymbolAddress((void**)&hWvg, g_hWvg);
    cudaGetSymbolAddress((void**)&hW1,  g_hW1);
    cudaGetSymbolAddress((void**)&hW2,  g_hW2);

    cudaFuncSetAttribute(hgemm_kernel, cudaFuncAttributeMaxDynamicSharedMemorySize, TGEMM_SMEM);

    const int nP4 = LNUM * DM * DM / 4;
    const int nF4 = LNUM * DM * FF / 4;
    dim3 g6(512, 1, 6);
    f2h_kernel6<<<g6, 256>>>((const float4*)Wq, (const float4*)Wk, (const float4*)Wv,
                             (const float4*)Wo, (const float4*)Wkg, (const float4*)Wvg,
                             (uint2*)hWq, (uint2*)hWk, (uint2*)hWv,
                             (uint2*)hWo, (uint2*)hWkg, (uint2*)hWvg, nP4);
    f2h_kernel<<<2048, 256>>>((const float4*)W1, (uint2*)hW1, nF4);
    f2h_kernel<<<2048, 256>>>((const float4*)W2, (uint2*)hW2, nF4);

    embed_kernel<<<S, 192>>>(x, (const float4*)word_emb, (const float4*)pos_emb,
                             (const float4*)emb_ln_s, (const float4*)emb_ln_b,
                             (float4*)h, (uint2*)h16);

    dim3 grid5  (DM / 128, S / 128, 5);
    dim3 gridP  (DM / 128, S / 128, 1);
    dim3 gridF1 (FF / 128, S / 128, 1);
    dim3 gridF2 (DM / 128, S / 128, 1);
    dim3 gridAtt(2 * CCH + NW, HNUM);

    for (int l = 0; l < LNUM; l++) {
        size_t wO  = (size_t)l * DM * DM;
        size_t bO  = (size_t)l * DM;
        size_t w1O = (size_t)l * DM * FF;
        size_t b1O = (size_t)l * FF;
        size_t w2O = (size_t)l * FF * DM;

        hgemm_kernel<<<grid5, 256, TGEMM_SMEM>>>(h16,
            hWq + wO, hWk + wO, hWv + wO, hWkg + wO, hWvg + wO,
            bq + bO, bk + bO, bv + bO, bkg + bO, bvg + bO,
            q16, k16, v16, kg16, vg16,
            S, DM, DM, DM, 0, SCALE, 0, 0b11111);
        attn_kernel<<<gridAtt, 256>>>(q16, k16, v16, h, Wqg + wO, bqg + bO,
                                      kg16, vg16, attn16);

        hgemm_kernel<<<gridP, 256, TGEMM_SMEM>>>(attn16,
            hWo + wO, hWo + wO, hWo + wO, hWo + wO, hWo + wO,
            bo + bO, bo + bO, bo + bO, bo + bO, bo + bO,
            y0, y0, y0, y0, y0,
            S, DM, DM, DM, 0, 1.0f, 0, 0);
        add_ln_kernel<<<S, 192>>>((const float4*)h, (const float4*)y0,
                                  (const float4*)(ln1s + bO), (const float4*)(ln1b + bO),
                                  (float4*)h, (uint2*)h16);

        hgemm_kernel<<<gridF1, 256, TGEMM_SMEM>>>(h16,
            hW1 + w1O, hW1 + w1O, hW1 + w1O, hW1 + w1O, hW1 + w1O,
            b1 + b1O, b1 + b1O, b1 + b1O, b1 + b1O, b1 + b1O,
            ffn16, ffn16, ffn16, ffn16, ffn16,
            S, FF, DM, DM, 0, 1.0f, 1, 0b11111);
        hgemm_kernel<<<gridF2, 256, TGEMM_SMEM>>>(ffn16,
            hW2 + w2O, hW2 + w2O, hW2 + w2O, hW2 + w2O, hW2 + w2O,
            b2 + bO, b2 + bO, b2 + bO, b2 + bO, b2 + bO,
            y0, y0, y0, y0, y0,
            S, DM, FF, FF, 0, 1.0f, 0, 0);
        add_ln_kernel<<<S, 192>>>((const float4*)h, (const float4*)y0,
                                  (const float4*)(ln2s + bO), (const float4*)(ln2b + bO),
                                  (float4*)h, (uint2*)h16);
    }

    head_kernel<<<NW, 128>>>(h, Wout, bout, out);
}

// round 17
// speedup vs baseline: 1.0739x; 1.0739x over previous
#include <cuda_runtime.h>
#include <cuda_fp16.h>
#include <math.h>
#include <stdint.h>

// ---------------- problem constants ----------------
#define S     4096
#define DM    768
#define FF    3072
#define HNUM  12
#define HD    64
#define WIN   256
#define CCH   16
#define NW    8
#define LNUM  12
#define OUTD  128
#define SCALE 0.125f

// ---------------- scratch ----------------
__device__ float g_h    [S*DM];
__device__ __half g_y16   [S*DM];
__device__ __half g_h16   [S*DM];
__device__ __half g_q16   [S*DM];
__device__ __half g_k16   [S*DM];
__device__ __half g_v16   [S*DM];
__device__ __half g_kg16  [S*DM];
__device__ __half g_vg16  [S*DM];
__device__ __half g_attn16[S*DM];
__device__ __half g_ffn16 [S*FF];

// fp16 weight copies
__device__ __half g_hWq [LNUM*DM*DM];
__device__ __half g_hWk [LNUM*DM*DM];
__device__ __half g_hWv [LNUM*DM*DM];
__device__ __half g_hWo [LNUM*DM*DM];
__device__ __half g_hWkg[LNUM*DM*DM];
__device__ __half g_hWvg[LNUM*DM*DM];
__device__ __half g_hW1 [LNUM*DM*FF];
__device__ __half g_hW2 [LNUM*FF*DM];

// ---------------- helpers ----------------
__device__ __forceinline__ float gelu_f(float x) {
    float x3 = x * x * x;
    return 0.5f * x * (1.0f + tanhf(0.7978845608028654f * (x + 0.044715f * x3)));
}

__device__ __forceinline__ unsigned pack_h2(float a, float b) {
    __half2 p = __float22half2_rn(make_float2(a, b));
    return *reinterpret_cast<unsigned*>(&p);
}

__device__ __forceinline__ void cp_async16(void* smem_dst, const void* gmem_src) {
    uint32_t dst = (uint32_t)__cvta_generic_to_shared(smem_dst);
    asm volatile("cp.async.ca.shared.global [%0], [%1], 16;" :: "r"(dst), "l"(gmem_src));
}

__device__ __forceinline__ void cp_async16z(void* smem_dst, const void* gmem_src, int src_sz) {
    uint32_t dst = (uint32_t)__cvta_generic_to_shared(smem_dst);
    asm volatile("cp.async.ca.shared.global [%0], [%1], 16, %2;"
                 :: "r"(dst), "l"(gmem_src), "r"(src_sz));
}

// ---------------- fp32 -> fp16 conversion, batched over z ----------------
__global__ void f2h_kernel6(const float4* in0, const float4* in1, const float4* in2,
                            const float4* in3, const float4* in4, const float4* in5,
                            uint2* out0, uint2* out1, uint2* out2,
                            uint2* out3, uint2* out4, uint2* out5, int n4)
{
    int z = blockIdx.z;
    const float4* in = (z == 0) ? in0 : (z == 1) ? in1 : (z == 2) ? in2 :
                       (z == 3) ? in3 : (z == 4) ? in4 : in5;
    uint2* out = (z == 0) ? out0 : (z == 1) ? out1 : (z == 2) ? out2 :
                 (z == 3) ? out3 : (z == 4) ? out4 : out5;
    for (int i = blockIdx.x * blockDim.x + threadIdx.x; i < n4; i += gridDim.x * blockDim.x) {
        float4 v = in[i];
        uint2 o;
        o.x = pack_h2(v.x, v.y);
        o.y = pack_h2(v.z, v.w);
        out[i] = o;
    }
}

__global__ void f2h_kernel(const float4* __restrict__ in, uint2* __restrict__ out, int n4)
{
    for (int i = blockIdx.x * blockDim.x + threadIdx.x; i < n4; i += gridDim.x * blockDim.x) {
        float4 v = in[i];
        uint2 o;
        o.x = pack_h2(v.x, v.y);
        o.y = pack_h2(v.z, v.w);
        out[i] = o;
    }
}

// ---------------- LN core: 192 threads, float4, single-pass sum/sumsq ----------------
__device__ __forceinline__ void ln_write(float4 v, const float4* __restrict__ ls4,
                                         const float4* __restrict__ lb4,
                                         float4* __restrict__ o, uint2* __restrict__ o16,
                                         size_t idx, int t)
{
    const int warp = t >> 5, lane = t & 31;
    __shared__ float ss[6], ss2[6];
    float sum = v.x + v.y + v.z + v.w;
    float sq  = v.x * v.x + v.y * v.y + v.z * v.z + v.w * v.w;
#pragma unroll
    for (int o_ = 16; o_ > 0; o_ >>= 1) {
        sum += __shfl_xor_sync(0xffffffffu, sum, o_);
        sq  += __shfl_xor_sync(0xffffffffu, sq,  o_);
    }
    if (lane == 0) { ss[warp] = sum; ss2[warp] = sq; }
    __syncthreads();
    float tot  = ss[0] + ss[1] + ss[2] + ss[3] + ss[4] + ss[5];
    float tot2 = ss2[0] + ss2[1] + ss2[2] + ss2[3] + ss2[4] + ss2[5];
    float mean = tot * (1.f / (float)DM);
    float var  = tot2 * (1.f / (float)DM) - mean * mean;
    float rstd = rsqrtf(var + 1e-5f);
    float4 lsv = ls4[t], lbv = lb4[t];
    float4 ov;
    ov.x = (v.x - mean) * rstd * lsv.x + lbv.x;
    ov.y = (v.y - mean) * rstd * lsv.y + lbv.y;
    ov.z = (v.z - mean) * rstd * lsv.z + lbv.z;
    ov.w = (v.w - mean) * rstd * lsv.w + lbv.w;
    o[idx] = ov;
    uint2 pk;
    pk.x = pack_h2(ov.x, ov.y);
    pk.y = pack_h2(ov.z, ov.w);
    o16[idx] = pk;
}

// ---------------- embedding + LN ----------------
__global__ void embed_kernel(const int* __restrict__ x, const float4* __restrict__ we,
                             const float4* __restrict__ pe, const float4* __restrict__ ls,
                             const float4* __restrict__ lb, float4* __restrict__ h,
                             uint2* __restrict__ h16)
{
    int s = blockIdx.x;
    int t = threadIdx.x;
    int r = s & 511, w = s >> 9;
    int id = (r == 0) ? 0 : x[w * 511 + r - 1];
    float4 a = we[(size_t)id * 192 + t];
    float4 b = pe[(size_t)s * 192 + t];
    float4 v = make_float4(a.x + b.x, a.y + b.y, a.z + b.z, a.w + b.w);
    ln_write(v, ls, lb, h, h16, (size_t)s * 192 + t, t);
}

// ---------------- residual add + LN (y in fp16) ----------------
__global__ void add_ln_kernel(const float4* __restrict__ x, const uint2* __restrict__ y16,
                              const float4* __restrict__ ls, const float4* __restrict__ lb,
                              float4* __restrict__ o, uint2* __restrict__ o16)
{
    int s = blockIdx.x;
    int t = threadIdx.x;
    size_t idx = (size_t)s * 192 + t;
    float4 a = x[idx];
    uint2 yp = y16[idx];
    float2 y0 = __half22float2(*reinterpret_cast<__half2*>(&yp.x));
    float2 y1 = __half22float2(*reinterpret_cast<__half2*>(&yp.y));
    float4 v = make_float4(a.x + y0.x, a.y + y0.y, a.z + y1.x, a.w + y1.y);
    ln_write(v, ls, lb, o, o16, idx, t);
}

// ---------------- fp16 tensor-core GEMM, cp.async 2-stage, batched over z ----------------
#define AS_H    9216
#define STG_H   17920
#define TGEMM_SMEM (2 * STG_H * 2)

__global__ __launch_bounds__(256, 2)
void hgemm_kernel(const __half* __restrict__ A,
                  const __half* B0, const __half* B1, const __half* B2,
                  const __half* B3, const __half* B4,
                  const float* bias0, const float* bias1, const float* bias2,
                  const float* bias3, const float* bias4,
                  void* C0, void* C1, void* C2, void* C3, void* C4,
                  int M, int N, int K, int lda,
                  float al0, int act, int outHalfMask)
{
    extern __shared__ __half sm[];

    const int z = blockIdx.z;
    const __half* B = (z == 0) ? B0 : (z == 1) ? B1 : (z == 2) ? B2 : (z == 3) ? B3 : B4;
    const float* bias = (z == 0) ? bias0 : (z == 1) ? bias1 : (z == 2) ? bias2 : (z == 3) ? bias3 : bias4;
    void* C = (z == 0) ? C0 : (z == 1) ? C1 : (z == 2) ? C2 : (z == 3) ? C3 : C4;
    const float alpha = (z == 0) ? al0 : 1.0f;
    const int outHalf = (outHalfMask >> z) & 1;

    const int tid  = threadIdx.x;
    const int lane = tid & 31;
    const int warp = tid >> 5;
    const int wm = warp >> 2;
    const int wn = warp & 3;

    const int bRow = blockIdx.y * 128;
    const int bCol = blockIdx.x * 128;

    float acc[4][4][4];
#pragma unroll
    for (int i = 0; i < 4; i++)
#pragma unroll
        for (int j = 0; j < 4; j++)
#pragma unroll
            for (int r = 0; r < 4; r++) acc[i][j][r] = 0.f;

    const int nk = K >> 6;

    {
        __half* as = sm;
        __half* bs = sm + AS_H;
#pragma unroll
        for (int p = 0; p < 4; p++) {
            int id = p * 256 + tid;
            int r = id >> 3, c = (id & 7) * 8;
            cp_async16(as + r * 72 + c, A + (size_t)(bRow + r) * lda + c);
        }
#pragma unroll
        for (int p = 0; p < 4; p++) {
            int id = p * 256 + tid;
            int r = id >> 4, c = (id & 15) * 8;
            cp_async16(bs + r * 136 + c, B + (size_t)r * N + bCol + c);
        }
        asm volatile("cp.async.commit_group;" ::);
    }

    for (int kt = 0; kt < nk; kt++) {
        asm volatile("cp.async.wait_group 0;" ::);
        __syncthreads();

        if (kt + 1 < nk) {
            const int k0 = (kt + 1) << 6;
            __half* as = sm + ((kt + 1) & 1) * STG_H;
            __half* bs = as + AS_H;
#pragma unroll
            for (int p = 0; p < 4; p++) {
                int id = p * 256 + tid;
                int r = id >> 3, c = (id & 7) * 8;
                cp_async16(as + r * 72 + c, A + (size_t)(bRow + r) * lda + k0 + c);
            }
#pragma unroll
            for (int p = 0; p < 4; p++) {
                int id = p * 256 + tid;
                int r = id >> 4, c = (id & 15) * 8;
                cp_async16(bs + r * 136 + c, B + (size_t)(k0 + r) * N + bCol + c);
            }
            asm volatile("cp.async.commit_group;" ::);
        }

        const __half* as = sm + (kt & 1) * STG_H;
        const __half* bs = as + AS_H;
#pragma unroll
        for (int kk = 0; kk < 64; kk += 16) {
            uint32_t af[4][4];
#pragma unroll
            for (int mi = 0; mi < 4; mi++) {
                uint32_t addr = (uint32_t)__cvta_generic_to_shared(
                    as + (wm * 64 + mi * 16 + (lane & 15)) * 72 + kk + (lane >> 4) * 8);
                asm volatile("ldmatrix.sync.aligned.m8n8.x4.shared.b16 {%0,%1,%2,%3}, [%4];"
                             : "=r"(af[mi][0]), "=r"(af[mi][1]), "=r"(af[mi][2]), "=r"(af[mi][3])
                             : "r"(addr));
            }
            uint32_t bfr[4][2];
#pragma unroll
            for (int nb = 0; nb < 2; nb++) {
                uint32_t addr = (uint32_t)__cvta_generic_to_shared(
                    bs + (kk + (lane & 15)) * 136 + wn * 32 + nb * 16 + (lane >> 4) * 8);
                uint32_t r0, r1, r2, r3;
                asm volatile("ldmatrix.sync.aligned.m8n8.x4.trans.shared.b16 {%0,%1,%2,%3}, [%4];"
                             : "=r"(r0), "=r"(r1), "=r"(r2), "=r"(r3)
                             : "r"(addr));
                bfr[nb * 2][0] = r0; bfr[nb * 2][1] = r1;
                bfr[nb * 2 + 1][0] = r2; bfr[nb * 2 + 1][1] = r3;
            }
#pragma unroll
            for (int mi = 0; mi < 4; mi++)
#pragma unroll
                for (int ni = 0; ni < 4; ni++) {
                    asm volatile(
                        "mma.sync.aligned.m16n8k16.row.col.f32.f16.f16.f32 "
                        "{%0,%1,%2,%3}, {%4,%5,%6,%7}, {%8,%9}, {%0,%1,%2,%3};"
                        : "+f"(acc[mi][ni][0]), "+f"(acc[mi][ni][1]),
                          "+f"(acc[mi][ni][2]), "+f"(acc[mi][ni][3])
                        : "r"(af[mi][0]), "r"(af[mi][1]), "r"(af[mi][2]), "r"(af[mi][3]),
                          "r"(bfr[ni][0]), "r"(bfr[ni][1]));
                }
        }
        __syncthreads();
    }

#pragma unroll
    for (int mi = 0; mi < 4; mi++) {
        int row0 = bRow + wm * 64 + mi * 16 + (lane >> 2);
#pragma unroll
        for (int ni = 0; ni < 4; ni++) {
            int col = bCol + wn * 32 + ni * 8 + (lane & 3) * 2;
            float b0 = bias[col], b1 = bias[col + 1];
            float v0 = (acc[mi][ni][0] + b0) * alpha;
            float v1 = (acc[mi][ni][1] + b1) * alpha;
            float v2 = (acc[mi][ni][2] + b0) * alpha;
            float v3 = (acc[mi][ni][3] + b1) * alpha;
            if (act == 1) { v0 = gelu_f(v0); v1 = gelu_f(v1); v2 = gelu_f(v2); v3 = gelu_f(v3); }
            if (outHalf) {
                __half* Ch = (__half*)C;
                *(uint32_t*)&Ch[(size_t)row0 * N + col]       = pack_h2(v0, v1);
                *(uint32_t*)&Ch[(size_t)(row0 + 8) * N + col] = pack_h2(v2, v3);
            } else {
                float* Cf = (float*)C;
                *(float2*)&Cf[(size_t)row0 * N + col]       = make_float2(v0, v1);
                *(float2*)&Cf[(size_t)(row0 + 8) * N + col] = make_float2(v2, v3);
            }
        }
    }
}

// ---------------- local attention (flash-style), 128 queries/block, 32-key tiles ----------------
__global__ __launch_bounds__(256)
void local_attn_mma(const __half* __restrict__ q, const __half* __restrict__ k,
                    const __half* __restrict__ v, __half* __restrict__ out)
{
    const int bx = blockIdx.x;
    const int c = bx >> 1, half = bx & 1;
    const int hh = blockIdx.y;
    const int tid = threadIdx.x;
    const int lane = tid & 31, warp = tid >> 5;
    const int hoff = hh * HD;
    const int qbase = c * WIN + half * 128;

    __shared__ __align__(16) __half Qs[128][72];
    __shared__ __align__(16) __half Ks[2][32][72];
    __shared__ __align__(16) __half Vs[2][32][72];

    const int st_hs = tid >> 7;
    const int st_j  = (tid & 127) >> 3;
    const int st_ch = (tid & 7) * 8;

    for (int i = tid; i < 1024; i += 256) {
        int row = i >> 3, ch = (i & 7) * 8;
        *(uint4*)&Qs[row][ch] = *(const uint4*)&q[(size_t)(qbase + row) * DM + hoff + ch];
    }

    {
        const __half* src = st_hs ? v : k;
#pragma unroll
        for (int rr = 0; rr < 2; rr++) {
            int row = st_j + rr * 16;
            bool valid = (row < 8);
            int kpos = valid ? row * 512 : 0;
            void* dst = st_hs ? (void*)&Vs[0][row][st_ch] : (void*)&Ks[0][row][st_ch];
            cp_async16z(dst, src + (size_t)kpos * DM + hoff + st_ch, valid ? 16 : 0);
        }
        asm volatile("cp.async.commit_group;" ::);
    }
    __syncthreads();

    uint32_t qf[4][4];
#pragma unroll
    for (int kt = 0; kt < 4; kt++) {
        uint32_t addr = (uint32_t)__cvta_generic_to_shared(
            &Qs[warp * 16 + (lane & 15)][kt * 16 + (lane >> 4) * 8]);
        asm volatile("ldmatrix.sync.aligned.m8n8.x4.shared.b16 {%0,%1,%2,%3}, [%4];"
                     : "=r"(qf[kt][0]), "=r"(qf[kt][1]), "=r"(qf[kt][2]), "=r"(qf[kt][3])
                     : "r"(addr));
    }

    float mrow[2] = { -1e30f, -1e30f }, lrow[2] = { 0.f, 0.f };
    float acc[8][4];
#pragma unroll
    for (int n8 = 0; n8 < 8; n8++)
#pragma unroll
        for (int r = 0; r < 4; r++) acc[n8][r] = 0.f;

    for (int t0 = 0; t0 <= 24; t0++) {
        const int cur = t0 & 1, nxt = cur ^ 1;

        asm volatile("cp.async.wait_group 0;" ::);
        __syncthreads();

        if (t0 < 24) {
            const __half* src = st_hs ? v : k;
#pragma unroll
            for (int rr = 0; rr < 2; rr++) {
                int row = st_j + rr * 16;
                int jg = t0 * 32 + row;
                int kpos = c * WIN + jg - WIN;
                bool valid = (kpos >= 0 && kpos < S);
                void* dst = st_hs ? (void*)&Vs[nxt][row][st_ch] : (void*)&Ks[nxt][row][st_ch];
                cp_async16z(dst, src + (size_t)(valid ? kpos : 0) * DM + hoff + st_ch,
                            valid ? 16 : 0);
            }
        }
        asm volatile("cp.async.commit_group;" ::);

        float sc[4][4];
#pragma unroll
        for (int nb = 0; nb < 4; nb++)
#pragma unroll
            for (int r = 0; r < 4; r++) sc[nb][r] = 0.f;
#pragma unroll
        for (int g = 0; g < 2; g++) {
            uint32_t kf[4][4];
#pragma unroll
            for (int kt = 0; kt < 4; kt++) {
                uint32_t addr = (uint32_t)__cvta_generic_to_shared(
                    &Ks[cur][g * 16 + (lane & 15)][kt * 16 + (lane >> 4) * 8]);
                asm volatile("ldmatrix.sync.aligned.m8n8.x4.shared.b16 {%0,%1,%2,%3}, [%4];"
                             : "=r"(kf[kt][0]), "=r"(kf[kt][1]), "=r"(kf[kt][2]), "=r"(kf[kt][3])
                             : "r"(addr));
            }
#pragma unroll
            for (int kt = 0; kt < 4; kt++) {
                asm volatile(
                    "mma.sync.aligned.m16n8k16.row.col.f32.f16.f16.f32 "
                    "{%0,%1,%2,%3}, {%4,%5,%6,%7}, {%8,%9}, {%0,%1,%2,%3};"
                    : "+f"(sc[g*2][0]), "+f"(sc[g*2][1]), "+f"(sc[g*2][2]), "+f"(sc[g*2][3])
                    : "r"(qf[kt][0]), "r"(qf[kt][1]), "r"(qf[kt][2]), "r"(qf[kt][3]),
                      "r"(kf[kt][0]), "r"(kf[kt][2]));
                asm volatile(
                    "mma.sync.aligned.m16n8k16.row.col.f32.f16.f16.f32 "
                    "{%0,%1,%2,%3}, {%4,%5,%6,%7}, {%8,%9}, {%0,%1,%2,%3};"
                    : "+f"(sc[g*2+1][0]), "+f"(sc[g*2+1][1]), "+f"(sc[g*2+1][2]), "+f"(sc[g*2+1][3])
                    : "r"(qf[kt][0]), "r"(qf[kt][1]), "r"(qf[kt][2]), "r"(qf[kt][3]),
                      "r"(kf[kt][1]), "r"(kf[kt][3]));
            }
        }

        uint32_t pa[2][4];
#pragma unroll
        for (int h = 0; h < 2; h++) {
            int qi = half * 128 + warp * 16 + (lane >> 2) + h * 8;
            int j0 = (lane & 3) * 2;
            float sv[8];
#pragma unroll
            for (int nb = 0; nb < 4; nb++) {
                sv[nb * 2]     = sc[nb][2 * h];
                sv[nb * 2 + 1] = sc[nb][2 * h + 1];
            }
#pragma unroll
            for (int e = 0; e < 8; e++) {
                int jj = (e >> 1) * 8 + j0 + (e & 1);
                bool valid;
                if (t0 == 0) valid = (jj < 8);
                else {
                    int jg = (t0 - 1) * 32 + jj;
                    int kp = c * WIN + jg - WIN;
                    valid = (jg >= qi) && (jg <= qi + 2 * WIN) && (kp >= 0) && (kp < S);
                }
                if (!valid) sv[e] = -1e30f;
            }
            float rmax = sv[0];
#pragma unroll
            for (int e = 1; e < 8; e++) rmax = fmaxf(rmax, sv[e]);
            rmax = fmaxf(rmax, __shfl_xor_sync(0xffffffffu, rmax, 1));
            rmax = fmaxf(rmax, __shfl_xor_sync(0xffffffffu, rmax, 2));
            float mnew = fmaxf(mrow[h], rmax);
            float scale = __expf(mrow[h] - mnew);
            float p[8], ls = 0.f;
#pragma unroll
            for (int e = 0; e < 8; e++) { p[e] = __expf(sv[e] - mnew); ls += p[e]; }
            ls += __shfl_xor_sync(0xffffffffu, ls, 1);
            ls += __shfl_xor_sync(0xffffffffu, ls, 2);
            lrow[h] = lrow[h] * scale + ls;
            mrow[h] = mnew;
#pragma unroll
            for (int n8 = 0; n8 < 8; n8++) {
                acc[n8][2 * h]     *= scale;
                acc[n8][2 * h + 1] *= scale;
            }
            pa[0][h]     = pack_h2(p[0], p[1]);
            pa[0][h + 2] = pack_h2(p[2], p[3]);
            pa[1][h]     = pack_h2(p[4], p[5]);
            pa[1][h + 2] = pack_h2(p[6], p[7]);
        }

#pragma unroll
        for (int ks = 0; ks < 2; ks++) {
#pragma unroll
            for (int nb = 0; nb < 4; nb++) {
                uint32_t addr = (uint32_t)__cvta_generic_to_shared(
                    &Vs[cur][ks * 16 + (lane & 15)][nb * 16 + (lane >> 4) * 8]);
                uint32_t r0, r1, r2, r3;
                asm volatile("ldmatrix.sync.aligned.m8n8.x4.trans.shared.b16 {%0,%1,%2,%3}, [%4];"
                             : "=r"(r0), "=r"(r1), "=r"(r2), "=r"(r3)
                             : "r"(addr));
                asm volatile(
                    "mma.sync.aligned.m16n8k16.row.col.f32.f16.f16.f32 "
                    "{%0,%1,%2,%3}, {%4,%5,%6,%7}, {%8,%9}, {%0,%1,%2,%3};"
                    : "+f"(acc[nb*2][0]), "+f"(acc[nb*2][1]), "+f"(acc[nb*2][2]), "+f"(acc[nb*2][3])
                    : "r"(pa[ks][0]), "r"(pa[ks][1]), "r"(pa[ks][2]), "r"(pa[ks][3]),
                      "r"(r0), "r"(r1));
                asm volatile(
                    "mma.sync.aligned.m16n8k16.row.col.f32.f16.f16.f32 "
                    "{%0,%1,%2,%3}, {%4,%5,%6,%7}, {%8,%9}, {%0,%1,%2,%3};"
                    : "+f"(acc[nb*2+1][0]), "+f"(acc[nb*2+1][1]), "+f"(acc[nb*2+1][2]), "+f"(acc[nb*2+1][3])
                    : "r"(pa[ks][0]), "r"(pa[ks][1]), "r"(pa[ks][2]), "r"(pa[ks][3]),
                      "r"(r2), "r"(r3));
            }
        }
    }

#pragma unroll
    for (int h = 0; h < 2; h++) {
        float inv = 1.f / lrow[h];
        int row = warp * 16 + (lane >> 2) + h * 8;
        size_t base = (size_t)(qbase + row) * DM + hoff;
#pragma unroll
        for (int n8 = 0; n8 < 8; n8++) {
            int dim = n8 * 8 + (lane & 3) * 2;
            *(uint32_t*)&out[base + dim] =
                pack_h2(acc[n8][2 * h] * inv, acc[n8][2 * h + 1] * inv);
        }
    }
}

// ---------------- global-token full attention (qg fused, fp16 kg/vg) ----------------
__global__ void global_attn_kernel(const float* __restrict__ h, const float* __restrict__ Wqg,
                                   const float* __restrict__ bqg,
                                   const __half* __restrict__ kg, const __half* __restrict__ vg,
                                   __half* __restrict__ out)
{
    int g = blockIdx.x, hh = blockIdx.y;
    int hoff = hh * HD;
    int tid = threadIdx.x;
    __shared__ float qs[HD];
    __shared__ float sc[S];
    __shared__ float red[256];

    {
        int d = tid & 63, part = tid >> 6;
        const float* hr = h + (size_t)(g * 512) * DM;
        float a = 0.f;
        for (int kk = part * 192; kk < (part + 1) * 192; kk++)
            a += hr[kk] * Wqg[(size_t)kk * DM + hoff + d];
        red[tid] = a; __syncthreads();
        if (tid < 64)
            qs[tid] = (red[tid] + red[tid + 64] + red[tid + 128] + red[tid + 192]
                       + bqg[hoff + tid]) * SCALE;
        __syncthreads();
    }

    float lmax = -1e30f;
    for (int i = 0; i < 16; i++) {
        int s = i * 256 + tid;
        const __half2* kr = (const __half2*)(kg + (size_t)s * DM + hoff);
        float a = 0.f;
#pragma unroll
        for (int d2 = 0; d2 < 32; d2++) {
            float2 f = __half22float2(kr[d2]);
            a += qs[d2 * 2] * f.x + qs[d2 * 2 + 1] * f.y;
        }
        sc[s] = a;
        lmax = fmaxf(lmax, a);
    }
    red[tid] = lmax; __syncthreads();
    for (int o = 128; o > 0; o >>= 1) { if (tid < o) red[tid] = fmaxf(red[tid], red[tid + o]); __syncthreads(); }
    float mx = red[0]; __syncthreads();

    float lsum = 0.f;
    for (int i = 0; i < 16; i++) {
        int s = i * 256 + tid;
        float p = __expf(sc[s] - mx);
        sc[s] = p;
        lsum += p;
    }
    red[tid] = lsum; __syncthreads();
    for (int o = 128; o > 0; o >>= 1) { if (tid < o) red[tid] += red[tid + o]; __syncthreads(); }
    float inv = 1.f / red[0]; __syncthreads();

    int d = tid & 63;
    int part = tid >> 6;
    float a = 0.f;
    for (int s = part * 1024; s < (part + 1) * 1024; s++)
        a += sc[s] * __half2float(vg[(size_t)s * DM + hoff + d]);
    red[tid] = a; __syncthreads();
    if (tid < 64) {
        float r = red[tid] + red[tid + 64] + red[tid + 128] + red[tid + 192];
        out[(size_t)(g * 512) * DM + hoff + d] = __float2half(r * inv);
    }
}

// ---------------- output head ----------------
__global__ void head_kernel(const float* __restrict__ h, const float* __restrict__ Wout,
                            const float* __restrict__ bout, float* __restrict__ out)
{
    int g = blockIdx.x;
    int o = threadIdx.x;
    const float* hr = h + (size_t)(g * 512) * DM;
    float a = bout[o];
    for (int d = 0; d < DM; d++) a += hr[d] * Wout[(size_t)d * OUTD + o];
    out[g * OUTD + o] = a;
}

// ---------------- driver ----------------
extern "C" void kernel_launch(void* const* d_in, const int* in_sizes, int n_in,
                              void* d_out, int out_size)
{
    (void)in_sizes; (void)n_in; (void)out_size;
    const int*   x        = (const int*)  d_in[0];
    const float* word_emb = (const float*)d_in[1];
    const float* pos_emb  = (const float*)d_in[2];
    const float* emb_ln_s = (const float*)d_in[3];
    const float* emb_ln_b = (const float*)d_in[4];
    const float* Wq  = (const float*)d_in[5];   const float* bq  = (const float*)d_in[6];
    const float* Wk  = (const float*)d_in[7];   const float* bk  = (const float*)d_in[8];
    const float* Wv  = (const float*)d_in[9];   const float* bv  = (const float*)d_in[10];
    const float* Wo  = (const float*)d_in[11];  const float* bo  = (const float*)d_in[12];
    const float* Wqg = (const float*)d_in[13];  const float* bqg = (const float*)d_in[14];
    const float* Wkg = (const float*)d_in[15];  const float* bkg = (const float*)d_in[16];
    const float* Wvg = (const float*)d_in[17];  const float* bvg = (const float*)d_in[18];
    const float* ln1s= (const float*)d_in[19];  const float* ln1b= (const float*)d_in[20];
    const float* W1  = (const float*)d_in[21];  const float* b1  = (const float*)d_in[22];
    const float* W2  = (const float*)d_in[23];  const float* b2  = (const float*)d_in[24];
    const float* ln2s= (const float*)d_in[25];  const float* ln2b= (const float*)d_in[26];
    const float* Wout= (const float*)d_in[27];  const float* bout= (const float*)d_in[28];
    float* out = (float*)d_out;

    float *h;
    __half *y16, *h16, *q16, *k16, *v16, *kg16, *vg16, *attn16, *ffn16;
    cudaGetSymbolAddress((void**)&h,    g_h);
    cudaGetSymbolAddress((void**)&y16,  g_y16);
    cudaGetSymbolAddress((void**)&h16,    g_h16);
    cudaGetSymbolAddress((void**)&q16,    g_q16);
    cudaGetSymbolAddress((void**)&k16,    g_k16);
    cudaGetSymbolAddress((void**)&v16,    g_v16);
    cudaGetSymbolAddress((void**)&kg16,   g_kg16);
    cudaGetSymbolAddress((void**)&vg16,   g_vg16);
    cudaGetSymbolAddress((void**)&attn16, g_attn16);
    cudaGetSymbolAddress((void**)&ffn16,  g_ffn16);

    __half *hWq, *hWk, *hWv, *hWo, *hWkg, *hWvg, *hW1, *hW2;
    cudaGetSymbolAddress((void**)&hWq,  g_hWq);
    cudaGetSymbolAddress((void**)&hWk,  g_hWk);
    cudaGetSymbolAddress((void**)&hWv,  g_hWv);
    cudaGetSymbolAddress((void**)&hWo,  g_hWo);
    cudaGetSymbolAddress((void**)&hWkg, g_hWkg);
    cudaGetSymbolAddress((void**)&hWvg, g_hWvg);
    cudaGetSymbolAddress((void**)&hW1,  g_hW1);
    cudaGetSymbolAddress((void**)&hW2,  g_hW2);

    cudaFuncSetAttribute(hgemm_kernel, cudaFuncAttributeMaxDynamicSharedMemorySize, TGEMM_SMEM);

    const int nP4 = LNUM * DM * DM / 4;
    const int nF4 = LNUM * DM * FF / 4;
    dim3 g6(512, 1, 6);
    f2h_kernel6<<<g6, 256>>>((const float4*)Wq, (const float4*)Wk, (const float4*)Wv,
                             (const float4*)Wo, (const float4*)Wkg, (const float4*)Wvg,
                             (uint2*)hWq, (uint2*)hWk, (uint2*)hWv,
                             (uint2*)hWo, (uint2*)hWkg, (uint2*)hWvg, nP4);
    f2h_kernel<<<2048, 256>>>((const float4*)W1, (uint2*)hW1, nF4);
    f2h_kernel<<<2048, 256>>>((const float4*)W2, (uint2*)hW2, nF4);

    embed_kernel<<<S, 192>>>(x, (const float4*)word_emb, (const float4*)pos_emb,
                             (const float4*)emb_ln_s, (const float4*)emb_ln_b,
                             (float4*)h, (uint2*)h16);

    dim3 grid5  (DM / 128, S / 128, 5);
    dim3 gridP  (DM / 128, S / 128, 1);
    dim3 gridF1 (FF / 128, S / 128, 1);
    dim3 gridF2 (DM / 128, S / 128, 1);
    dim3 gridAtt(2 * CCH, HNUM);
    dim3 gridGA (NW, HNUM);

    for (int l = 0; l < LNUM; l++) {
        size_t wO  = (size_t)l * DM * DM;
        size_t bO  = (size_t)l * DM;
        size_t w1O = (size_t)l * DM * FF;
        size_t b1O = (size_t)l * FF;
        size_t w2O = (size_t)l * FF * DM;

        hgemm_kernel<<<grid5, 256, TGEMM_SMEM>>>(h16,
            hWq + wO, hWk + wO, hWv + wO, hWkg + wO, hWvg + wO,
            bq + bO, bk + bO, bv + bO, bkg + bO, bvg + bO,
            q16, k16, v16, kg16, vg16,
            S, DM, DM, DM, SCALE, 0, 0b11111);
        local_attn_mma<<<gridAtt, 256>>>(q16, k16, v16, attn16);
        global_attn_kernel<<<gridGA, 256>>>(h, Wqg + wO, bqg + bO, kg16, vg16, attn16);

        hgemm_kernel<<<gridP, 256, TGEMM_SMEM>>>(attn16,
            hWo + wO, hWo + wO, hWo + wO, hWo + wO, hWo + wO,
            bo + bO, bo + bO, bo + bO, bo + bO, bo + bO,
            y16, y16, y16, y16, y16,
            S, DM, DM, DM, 1.0f, 0, 0b11111);
        add_ln_kernel<<<S, 192>>>((const float4*)h, (const uint2*)y16,
                                  (const float4*)(ln1s + bO), (const float4*)(ln1b + bO),
                                  (float4*)h, (uint2*)h16);

        hgemm_kernel<<<gridF1, 256, TGEMM_SMEM>>>(h16,
            hW1 + w1O, hW1 + w1O, hW1 + w1O, hW1 + w1O, hW1 + w1O,
            b1 + b1O, b1 + b1O, b1 + b1O, b1 + b1O, b1 + b1O,
            ffn16, ffn16, ffn16, ffn16, ffn16,
            S, FF, DM, DM, 1.0f, 1, 0b11111);
        hgemm_kernel<<<gridF2, 256, TGEMM_SMEM>>>(ffn16,
            hW2 + w2O, hW2 + w2O, hW2 + w2O, hW2 + w2O, hW2 + w2O,
            b2 + bO, b2 + bO, b2 + bO, b2 + bO, b2 + bO,
            y16, y16, y16, y16, y16,
            S, DM, FF, FF, 1.0f, 0, 0b11111);
        add_ln_kernel<<<S, 192>>>((const float4*)h, (const uint2*)y16,
                                  (const float4*)(ln2s + bO), (const float4*)(ln2b + bO),
                                  (float4*)h, (uint2*)h16);
    }

    head_kernel<<<NW, 128>>>(h, Wout, bout, out);
}